// round 3
// baseline (speedup 1.0000x reference)
#include <cuda_runtime.h>
#include <cstdint>

#define TT 2048
#define BB 32
#define NN 1024

// ---------------- scratch (device globals; no allocation allowed) ----------
__device__ float g_apart[8u  * BB * NN];   // split-K partials, first GEMM
__device__ float g_fpart[16u * BB * NN];   // split-K partials, final GEMM
__device__ float g_dec   [BB * NN];        // dec_feature
__device__ float g_scores[BB * TT];
__device__ float g_attn  [BB * TT];
__device__ float g_cpart [32u * BB * NN];  // content partials (32 t-chunks)
__device__ float g_content[BB * NN];

__device__ __forceinline__ float fast_tanh(float x) {
    // tanh(x) = 1 - 2/(exp(2x)+1); exp->inf => 0 => +1, exp->0 => -1. ~1e-7 rel.
    float e = __expf(2.0f * x);
    return 1.0f - __fdividef(2.0f, e + 1.0f);
}

// ---------------------------------------------------------------------------
// Split-K GEMM: part[kchunk][b][n] = sum_{k in chunk} S[b][k] * W[n][k]
// which=0: S = hx (K = NN), output g_apart.
// which=1: S = [g_content | hx] virtual concat (K = 2*NN), output g_fpart.
// g_content is referenced IN DEVICE CODE (passing a __device__ symbol as a
// host-side launch arg silently binds the zero host shadow via ATS on GB300 —
// that was the R1/R2 bug).
// Block tile: all 32 b x 32 n x 128 k. 256 threads, 2x2 register tile.
// ---------------------------------------------------------------------------
__global__ __launch_bounds__(256) void gemm32_partial(
    const float* __restrict__ hx,
    const float* __restrict__ W, int K, int which)
{
    __shared__ float sS[128 * 34];  // [k][b], stride 34 keeps 8B alignment
    __shared__ float sW[128 * 34];  // [k][n_local]
    const int tid = threadIdx.x;
    const int n0  = blockIdx.x * 32;
    const int k0  = blockIdx.y * 128;

    #pragma unroll
    for (int p = 0; p < 16; p++) {
        int i = tid + p * 256;          // 4096 elems: 32 b x 128 k
        int b = i >> 7, c = i & 127;
        int kg = k0 + c;
        float val;
        if (which == 0)       val = hx[b * NN + kg];
        else if (kg < NN)     val = g_content[b * NN + kg];
        else                  val = hx[b * NN + kg - NN];
        sS[c * 34 + b] = val;
    }
    #pragma unroll
    for (int p = 0; p < 16; p++) {
        int i = tid + p * 256;          // 32 n x 128 k
        int nl = i >> 7, c = i & 127;
        sW[c * 34 + nl] = W[(size_t)(n0 + nl) * K + k0 + c];
    }
    __syncthreads();

    const int b0  = (tid & 15) * 2;
    const int nl0 = (tid >> 4) * 2;
    float a00 = 0.f, a01 = 0.f, a10 = 0.f, a11 = 0.f;
    #pragma unroll 8
    for (int k = 0; k < 128; k++) {
        float2 d = *(const float2*)&sS[k * 34 + b0];
        float2 w = *(const float2*)&sW[k * 34 + nl0];
        a00 += d.x * w.x;  a01 += d.x * w.y;
        a10 += d.y * w.x;  a11 += d.y * w.y;
    }

    float* part = (which ? g_fpart : g_apart) + (size_t)blockIdx.y * (BB * NN);
    part[(b0 + 0) * NN + n0 + nl0 + 0] = a00;
    part[(b0 + 0) * NN + n0 + nl0 + 1] = a01;
    part[(b0 + 1) * NN + n0 + nl0 + 0] = a10;
    part[(b0 + 1) * NN + n0 + nl0 + 1] = a11;
}

// dec_feature = sum of 8 k-chunk partials + Ws_b
__global__ __launch_bounds__(256) void combine_dec(const float* __restrict__ Ws_b)
{
    int i = blockIdx.x * 256 + threadIdx.x;     // 32768 threads
    float s = Ws_b[i & (NN - 1)];
    #pragma unroll
    for (int c = 0; c < 8; c++) s += g_apart[c * (BB * NN) + i];
    g_dec[i] = s;
}

// ---------------------------------------------------------------------------
// scores[b,t] = sum_n tanh(ef[t,b,n] + dec[b,n]) * v[n] + vb   (256MB stream)
// grid (TT/16, BB), 256 threads; each block: 16 t-rows of one b.
// ---------------------------------------------------------------------------
__global__ __launch_bounds__(256) void scores_kernel(
    const float* __restrict__ ef, const float* __restrict__ vw,
    const float* __restrict__ vb)
{
    const int b   = blockIdx.y;
    const int t0  = blockIdx.x * 16;
    const int tid = threadIdx.x;
    __shared__ float s_red[16 * 8];

    float4 d = reinterpret_cast<const float4*>(g_dec + b * NN)[tid];
    float4 v = reinterpret_cast<const float4*>(vw)[tid];
    const int warp = tid >> 5, lane = tid & 31;

    #pragma unroll
    for (int r = 0; r < 16; r++) {
        size_t row = ((size_t)(t0 + r) * BB + b) * NN;
        float4 x = reinterpret_cast<const float4*>(ef + row)[tid];
        float p = fast_tanh(x.x + d.x) * v.x
                + fast_tanh(x.y + d.y) * v.y
                + fast_tanh(x.z + d.z) * v.z
                + fast_tanh(x.w + d.w) * v.w;
        #pragma unroll
        for (int o = 16; o; o >>= 1) p += __shfl_xor_sync(0xffffffffu, p, o);
        if (lane == 0) s_red[r * 8 + warp] = p;
    }
    __syncthreads();
    if (tid < 16) {
        float s = vb[0];
        #pragma unroll
        for (int w = 0; w < 8; w++) s += s_red[tid * 8 + w];
        g_scores[b * TT + t0 + tid] = s;
    }
}

// attn[b,:] = softmax(scores[b,:]) * mask[b,:]   (one block per b)
__global__ __launch_bounds__(256) void softmax_kernel(const float* __restrict__ mask)
{
    const int b = blockIdx.x, tid = threadIdx.x;
    __shared__ float red[8];
    __shared__ float s_max, s_sum;
    const int warp = tid >> 5, lane = tid & 31;

    float m = -1e30f;
    for (int i = tid; i < TT; i += 256) m = fmaxf(m, g_scores[b * TT + i]);
    #pragma unroll
    for (int o = 16; o; o >>= 1) m = fmaxf(m, __shfl_xor_sync(0xffffffffu, m, o));
    if (lane == 0) red[warp] = m;
    __syncthreads();
    if (tid == 0) {
        float mm = red[0];
        #pragma unroll
        for (int w = 1; w < 8; w++) mm = fmaxf(mm, red[w]);
        s_max = mm;
    }
    __syncthreads();
    const float bm = s_max;

    float s = 0.f;
    for (int i = tid; i < TT; i += 256) s += __expf(g_scores[b * TT + i] - bm);
    #pragma unroll
    for (int o = 16; o; o >>= 1) s += __shfl_xor_sync(0xffffffffu, s, o);
    __syncthreads();                 // red safe to reuse now
    if (lane == 0) red[warp] = s;
    __syncthreads();
    if (tid == 0) {
        float ss = 0.f;
        #pragma unroll
        for (int w = 0; w < 8; w++) ss += red[w];
        s_sum = ss;
    }
    __syncthreads();
    const float inv = 1.0f / s_sum;

    for (int i = tid; i < TT; i += 256)
        g_attn[b * TT + i] = __expf(g_scores[b * TT + i] - bm) * inv * mask[b * TT + i];
}

// ---------------------------------------------------------------------------
// content partials: cpart[ch][b][n] = sum_{t in chunk of 64} attn[b,t]*eo[t,b,n]
// grid (32 chunks, 32 b), 256 threads; thread owns float4 accumulator.
// ---------------------------------------------------------------------------
__global__ __launch_bounds__(256) void content_partial_kernel(
    const float* __restrict__ eo)
{
    const int b = blockIdx.y, ch = blockIdx.x, tid = threadIdx.x;
    __shared__ float sa[64];
    if (tid < 64) sa[tid] = g_attn[b * TT + ch * 64 + tid];
    __syncthreads();

    float4 acc = make_float4(0.f, 0.f, 0.f, 0.f);
    size_t base = (((size_t)ch * 64) * BB + b) * NN;
    #pragma unroll 4
    for (int r = 0; r < 64; r++) {
        float a = sa[r];
        float4 x = reinterpret_cast<const float4*>(eo + base + (size_t)r * BB * NN)[tid];
        acc.x += a * x.x;  acc.y += a * x.y;
        acc.z += a * x.z;  acc.w += a * x.w;
    }
    reinterpret_cast<float4*>(g_cpart + ((size_t)ch * BB + b) * NN)[tid] = acc;
}

__global__ __launch_bounds__(256) void combine_content()
{
    int i = blockIdx.x * 256 + threadIdx.x;
    float s = 0.f;
    #pragma unroll
    for (int c = 0; c < 32; c++) s += g_cpart[c * (BB * NN) + i];
    g_content[i] = s;
}

// out = tanh(sum of 16 k-chunk partials + lin_b)
__global__ __launch_bounds__(256) void combine_out(
    const float* __restrict__ lin_b, float* __restrict__ out)
{
    int i = blockIdx.x * 256 + threadIdx.x;
    float s = lin_b[i & (NN - 1)];
    #pragma unroll
    for (int c = 0; c < 16; c++) s += g_fpart[c * (BB * NN) + i];
    out[i] = fast_tanh(s);
}

// ---------------------------------------------------------------------------
extern "C" void kernel_launch(void* const* d_in, const int* in_sizes, int n_in,
                              void* d_out, int out_size)
{
    // Metadata/dict order (authoritative):
    const float* decoder_hx      = (const float*)d_in[0];
    const float* encoder_outputs = (const float*)d_in[1];
    const float* encoder_feature = (const float*)d_in[2];
    const float* mask_tensor     = (const float*)d_in[3];
    const float* Ws_b            = (const float*)d_in[5];
    const float* Ws_w            = (const float*)d_in[4];
    const float* v_w             = (const float*)d_in[6];
    const float* v_b             = (const float*)d_in[7];
    const float* lin_w           = (const float*)d_in[8];
    const float* lin_b           = (const float*)d_in[9];
    float* out = (float*)d_out;

    // 1) dec_feature = decoder_hx @ Ws_w^T + Ws_b  (split-K: 8 chunks)
    gemm32_partial<<<dim3(NN / 32, 8), 256>>>(decoder_hx, Ws_w, NN, 0);
    combine_dec<<<(BB * NN) / 256, 256>>>(Ws_b);

    // 2) scores (streams 256MB encoder_feature)
    scores_kernel<<<dim3(TT / 16, BB), 256>>>(encoder_feature, v_w, v_b);

    // 3) softmax * mask
    softmax_kernel<<<BB, 256>>>(mask_tensor);

    // 4) content vector (streams 256MB encoder_outputs), deterministic partials
    content_partial_kernel<<<dim3(32, BB), 256>>>(encoder_outputs);
    combine_content<<<(BB * NN) / 256, 256>>>();

    // 5) out = tanh([content|hx] @ lin_w^T + lin_b); g_content read in-device
    gemm32_partial<<<dim3(NN / 32, 16), 256>>>(decoder_hx, lin_w, 2 * NN, 1);
    combine_out<<<(BB * NN) / 256, 256>>>(lin_b, out);

    (void)in_sizes; (void)n_in; (void)out_size;
}

// round 4
// speedup vs baseline: 1.0533x; 1.0533x over previous
#include <cuda_runtime.h>
#include <cstdint>

#define TT 2048
#define BB 32
#define NN 1024

// ---------------- scratch (device globals; no allocation allowed) ----------
__device__ float g_apart[8u  * BB * NN];   // split-K partials, first GEMM
__device__ float g_fpart[16u * BB * NN];   // split-K partials, final GEMM
__device__ float g_scores[BB * TT];
__device__ float2 g_stats[BB];             // {rowmax, 1/sum}
__device__ float g_cpart [32u * BB * NN];  // content partials (32 t-chunks)
__device__ float g_content[BB * NN];

__device__ __forceinline__ float fast_tanh(float x) {
    // tanh(x) = 1 - 2/(exp(2x)+1). ~1e-7 rel.
    float e = __expf(2.0f * x);
    return 1.0f - __fdividef(2.0f, e + 1.0f);
}

// ---------------------------------------------------------------------------
// Split-K GEMM: part[kchunk][b][n] = sum_{k in chunk} S[b][k] * W[n][k]
// which=0: S = hx (K = NN) -> g_apart.
// which=1: S = [g_content | hx] (K = 2*NN) -> g_fpart. g_content referenced in
// DEVICE code only (host-side __device__-symbol args bind the zero host shadow
// via ATS on GB300 — the R1/R2 bug).
// ---------------------------------------------------------------------------
__global__ __launch_bounds__(256) void gemm32_partial(
    const float* __restrict__ hx,
    const float* __restrict__ W, int K, int which)
{
    __shared__ float sS[128 * 34];  // [k][b]
    __shared__ float sW[128 * 34];  // [k][n_local]
    const int tid = threadIdx.x;
    const int n0  = blockIdx.x * 32;
    const int k0  = blockIdx.y * 128;

    #pragma unroll
    for (int p = 0; p < 16; p++) {
        int i = tid + p * 256;          // 32 b x 128 k
        int b = i >> 7, c = i & 127;
        int kg = k0 + c;
        float val;
        if (which == 0)       val = hx[b * NN + kg];
        else if (kg < NN)     val = g_content[b * NN + kg];
        else                  val = hx[b * NN + kg - NN];
        sS[c * 34 + b] = val;
    }
    #pragma unroll
    for (int p = 0; p < 16; p++) {
        int i = tid + p * 256;          // 32 n x 128 k
        int nl = i >> 7, c = i & 127;
        sW[c * 34 + nl] = W[(size_t)(n0 + nl) * K + k0 + c];
    }
    __syncthreads();

    const int b0  = (tid & 15) * 2;
    const int nl0 = (tid >> 4) * 2;
    float a00 = 0.f, a01 = 0.f, a10 = 0.f, a11 = 0.f;
    #pragma unroll 8
    for (int k = 0; k < 128; k++) {
        float2 d = *(const float2*)&sS[k * 34 + b0];
        float2 w = *(const float2*)&sW[k * 34 + nl0];
        a00 += d.x * w.x;  a01 += d.x * w.y;
        a10 += d.y * w.x;  a11 += d.y * w.y;
    }

    float* part = (which ? g_fpart : g_apart) + (size_t)blockIdx.y * (BB * NN);
    part[(b0 + 0) * NN + n0 + nl0 + 0] = a00;
    part[(b0 + 0) * NN + n0 + nl0 + 1] = a01;
    part[(b0 + 1) * NN + n0 + nl0 + 0] = a10;
    part[(b0 + 1) * NN + n0 + nl0 + 1] = a11;
}

// ---------------------------------------------------------------------------
// scores[b,t] = sum_n tanh(ef[t,b,n] + dec[b,n]) * v[n] + vb
// dec[b,n] = Ws_b[n] + sum of 8 g_apart chunks (fused combine_dec).
// Mainloop keeps 16 independent per-row partials (no shuffles inside loop);
// single deferred smem reduction.
// ---------------------------------------------------------------------------
__global__ __launch_bounds__(256) void scores_kernel(
    const float* __restrict__ ef, const float* __restrict__ vw,
    const float* __restrict__ vb, const float* __restrict__ Ws_b)
{
    const int b   = blockIdx.y;
    const int t0  = blockIdx.x * 16;
    const int tid = threadIdx.x;
    __shared__ float sred[16 * 256];

    // dec (fused split-K combine + bias): L2-resident loads
    float4 d = reinterpret_cast<const float4*>(Ws_b)[tid];
    #pragma unroll
    for (int c = 0; c < 8; c++) {
        float4 p = reinterpret_cast<const float4*>(g_apart + c * (BB * NN) + b * NN)[tid];
        d.x += p.x; d.y += p.y; d.z += p.z; d.w += p.w;
    }
    float4 v = reinterpret_cast<const float4*>(vw)[tid];

    float pr[16];
    #pragma unroll
    for (int r = 0; r < 16; r++) {
        size_t row = ((size_t)(t0 + r) * BB + b) * NN;
        float4 x = reinterpret_cast<const float4*>(ef + row)[tid];
        pr[r] = fast_tanh(x.x + d.x) * v.x
              + fast_tanh(x.y + d.y) * v.y
              + fast_tanh(x.z + d.z) * v.z
              + fast_tanh(x.w + d.w) * v.w;
    }
    #pragma unroll
    for (int r = 0; r < 16; r++) sred[r * 256 + tid] = pr[r];
    __syncthreads();

    // 8 warps x 2 rows each; stride-32 LDS (conflict-free) + warp shuffle
    const int warp = tid >> 5, lane = tid & 31;
    #pragma unroll
    for (int rr = 0; rr < 2; rr++) {
        int r = warp * 2 + rr;
        float s = 0.f;
        #pragma unroll
        for (int j = 0; j < 8; j++) s += sred[r * 256 + lane + 32 * j];
        #pragma unroll
        for (int o = 16; o; o >>= 1) s += __shfl_xor_sync(0xffffffffu, s, o);
        if (lane == 0) g_scores[b * TT + t0 + r] = s + vb[0];
    }
}

// per-b softmax stats: g_stats[b] = {max, 1/sum}. grid 32 x 1024 threads.
__global__ __launch_bounds__(1024) void reduce_softmax_kernel()
{
    const int b = blockIdx.x, tid = threadIdx.x;
    __shared__ float red[32];
    __shared__ float s_bm;
    const int warp = tid >> 5, lane = tid & 31;

    float s0 = g_scores[b * TT + tid];
    float s1 = g_scores[b * TT + tid + 1024];

    float m = fmaxf(s0, s1);
    #pragma unroll
    for (int o = 16; o; o >>= 1) m = fmaxf(m, __shfl_xor_sync(0xffffffffu, m, o));
    if (lane == 0) red[warp] = m;
    __syncthreads();
    if (tid < 32) {
        float mm = red[lane];
        #pragma unroll
        for (int o = 16; o; o >>= 1) mm = fmaxf(mm, __shfl_xor_sync(0xffffffffu, mm, o));
        if (tid == 0) s_bm = mm;
    }
    __syncthreads();
    const float bm = s_bm;

    float s = __expf(s0 - bm) + __expf(s1 - bm);
    #pragma unroll
    for (int o = 16; o; o >>= 1) s += __shfl_xor_sync(0xffffffffu, s, o);
    __syncthreads();
    if (lane == 0) red[warp] = s;
    __syncthreads();
    if (tid < 32) {
        float ss = red[lane];
        #pragma unroll
        for (int o = 16; o; o >>= 1) ss += __shfl_xor_sync(0xffffffffu, ss, o);
        if (tid == 0) g_stats[b] = make_float2(bm, 1.0f / ss);
    }
}

// ---------------------------------------------------------------------------
// content partials with inline attn: attn[b,t] = exp(s-bm)*inv*mask[b,t]
// cpart[ch][b][n] = sum_{t in 64-chunk} attn[b,t] * eo[t,b,n]
// ---------------------------------------------------------------------------
__global__ __launch_bounds__(256) void content_partial_kernel(
    const float* __restrict__ eo, const float* __restrict__ mask)
{
    const int b = blockIdx.y, ch = blockIdx.x, tid = threadIdx.x;
    __shared__ float sa[64];
    if (tid < 64) {
        int t = ch * 64 + tid;
        float2 st = g_stats[b];
        sa[tid] = __expf(g_scores[b * TT + t] - st.x) * st.y * mask[b * TT + t];
    }
    __syncthreads();

    float4 acc = make_float4(0.f, 0.f, 0.f, 0.f);
    size_t base = (((size_t)ch * 64) * BB + b) * NN;
    #pragma unroll 4
    for (int r = 0; r < 64; r++) {
        float a = sa[r];
        float4 x = reinterpret_cast<const float4*>(eo + base + (size_t)r * BB * NN)[tid];
        acc.x += a * x.x;  acc.y += a * x.y;
        acc.z += a * x.z;  acc.w += a * x.w;
    }
    reinterpret_cast<float4*>(g_cpart + ((size_t)ch * BB + b) * NN)[tid] = acc;
}

__global__ __launch_bounds__(256) void combine_content()
{
    int i = blockIdx.x * 256 + threadIdx.x;
    float s = 0.f;
    #pragma unroll
    for (int c = 0; c < 32; c++) s += g_cpart[c * (BB * NN) + i];
    g_content[i] = s;
}

// out = tanh(sum of 16 k-chunk partials + lin_b)
__global__ __launch_bounds__(256) void combine_out(
    const float* __restrict__ lin_b, float* __restrict__ out)
{
    int i = blockIdx.x * 256 + threadIdx.x;
    float s = lin_b[i & (NN - 1)];
    #pragma unroll
    for (int c = 0; c < 16; c++) s += g_fpart[c * (BB * NN) + i];
    out[i] = fast_tanh(s);
}

// ---------------------------------------------------------------------------
extern "C" void kernel_launch(void* const* d_in, const int* in_sizes, int n_in,
                              void* d_out, int out_size)
{
    const float* decoder_hx      = (const float*)d_in[0];
    const float* encoder_outputs = (const float*)d_in[1];
    const float* encoder_feature = (const float*)d_in[2];
    const float* mask_tensor     = (const float*)d_in[3];
    const float* Ws_w            = (const float*)d_in[4];
    const float* Ws_b            = (const float*)d_in[5];
    const float* v_w             = (const float*)d_in[6];
    const float* v_b             = (const float*)d_in[7];
    const float* lin_w           = (const float*)d_in[8];
    const float* lin_b           = (const float*)d_in[9];
    float* out = (float*)d_out;

    // 1) dec_feature split-K partials
    gemm32_partial<<<dim3(NN / 32, 8), 256>>>(decoder_hx, Ws_w, NN, 0);

    // 2) scores (streams 256MB), combine_dec fused
    scores_kernel<<<dim3(TT / 16, BB), 256>>>(encoder_feature, v_w, v_b, Ws_b);

    // 3) softmax stats only (attn applied inline downstream)
    reduce_softmax_kernel<<<BB, 1024>>>();

    // 4) content vector (streams 256MB), attn computed inline
    content_partial_kernel<<<dim3(32, BB), 256>>>(encoder_outputs, mask_tensor);
    combine_content<<<(BB * NN) / 256, 256>>>();

    // 5) out = tanh([content|hx] @ lin_w^T + lin_b)
    gemm32_partial<<<dim3(NN / 32, 16), 256>>>(decoder_hx, lin_w, 2 * NN, 1);
    combine_out<<<(BB * NN) / 256, 256>>>(lin_b, out);

    (void)in_sizes; (void)n_in; (void)out_size;
}